// round 1
// baseline (speedup 1.0000x reference)
#include <cuda_runtime.h>
#include <math.h>

// ---------------- static problem config ----------------
#define TOKENS   100352      // 32 * 56 * 56  == 2048 windows * 49
#define CDIM     256
#define SDIM     49
#define HEADS    8
#define DHEAD    32
#define IMG      56
#define WIN      7
#define SHIFT    3
#define NMLP     1024
#define NWINTOT  16384       // 2048 windows * 8 heads (attention blocks)
#define SCALE    0.17677669529663687f   // 32^-0.5

// ---------------- device scratch (no allocations allowed) ----------------
__device__ float g_xw  [TOKENS * CDIM];        // LN'd, shifted+partitioned input
__device__ float g_qkv [TOKENS * 3 * CDIM];    // qkv projections (window order)
__device__ float g_attn[TOKENS * CDIM];        // attention output (window order)
__device__ float g_x1  [TOKENS * CDIM];        // x + attn branch (token order)
__device__ float g_xn2 [TOKENS * CDIM];        // LN2 output
__device__ float g_h   [TOKENS * NMLP];        // MLP hidden

// window-order row -> token-order row (roll+partition == reverse+unroll mapping)
__device__ __forceinline__ int rowmap(int r) {
    int bw = r / 49;
    int s  = r - bw * 49;
    int b    = bw >> 6;
    int widx = bw & 63;
    int sy = s / 7;
    int sx = s - sy * 7;
    int sh_h = ((widx >> 3) * 7) + sy;
    int sh_w = ((widx & 7) * 7) + sx;
    int oh = sh_h + SHIFT; if (oh >= IMG) oh -= IMG;
    int ow = sh_w + SHIFT; if (ow >= IMG) ow -= IMG;
    return b * (IMG * IMG) + oh * IMG + ow;
}

// ---------------- LayerNorm (warp per token), optional gather permute ----------------
template<bool GATHER>
__global__ void ln_kernel(const float* __restrict__ x,
                          const float* __restrict__ gamma,
                          const float* __restrict__ beta,
                          float* __restrict__ out)
{
    int gw   = (blockIdx.x * blockDim.x + threadIdx.x) >> 5;  // token (output row)
    int lane = threadIdx.x & 31;
    if (gw >= TOKENS) return;

    int src = GATHER ? rowmap(gw) : gw;
    const float4* xr = (const float4*)(x + (size_t)src * CDIM);
    float4 v0 = xr[lane];
    float4 v1 = xr[lane + 32];

    float sum = v0.x + v0.y + v0.z + v0.w + v1.x + v1.y + v1.z + v1.w;
    float sq  = v0.x*v0.x + v0.y*v0.y + v0.z*v0.z + v0.w*v0.w
              + v1.x*v1.x + v1.y*v1.y + v1.z*v1.z + v1.w*v1.w;
#pragma unroll
    for (int o = 16; o; o >>= 1) {
        sum += __shfl_xor_sync(0xffffffffu, sum, o);
        sq  += __shfl_xor_sync(0xffffffffu, sq,  o);
    }
    float mu   = sum * (1.0f / 256.0f);
    float var  = sq * (1.0f / 256.0f) - mu * mu;
    float rstd = rsqrtf(var + 1e-5f);

    float4 g0 = ((const float4*)gamma)[lane];
    float4 g1 = ((const float4*)gamma)[lane + 32];
    float4 b0 = ((const float4*)beta )[lane];
    float4 b1 = ((const float4*)beta )[lane + 32];

    float4 o0, o1;
    o0.x = (v0.x - mu) * rstd * g0.x + b0.x;
    o0.y = (v0.y - mu) * rstd * g0.y + b0.y;
    o0.z = (v0.z - mu) * rstd * g0.z + b0.z;
    o0.w = (v0.w - mu) * rstd * g0.w + b0.w;
    o1.x = (v1.x - mu) * rstd * g1.x + b1.x;
    o1.y = (v1.y - mu) * rstd * g1.y + b1.y;
    o1.z = (v1.z - mu) * rstd * g1.z + b1.z;
    o1.w = (v1.w - mu) * rstd * g1.w + b1.w;

    float4* orow = (float4*)(out + (size_t)gw * CDIM);
    orow[lane]      = o0;
    orow[lane + 32] = o1;
}

// ---------------- 64x64x16 fp32 SIMT GEMM, C = A@B + bias, fused epilogues ----------------
// EPI 0: plain store
// EPI 1: exact GELU
// EPI 2: scatter rows via rowmap, add residual (res read at scattered row)
// EPI 3: add residual at identity row
template<int EPI>
__global__ void gemm64(const float* __restrict__ A,
                       const float* __restrict__ B,
                       const float* __restrict__ bias,
                       float* __restrict__ Cd,
                       const float* __restrict__ res,
                       int N, int K)
{
    __shared__ float As[16][68];   // padded: conflict-free transposed stores
    __shared__ float Bs[16][64];

    int tid = threadIdx.x;
    int tx  = tid & 15;
    int ty  = tid >> 4;
    int bm  = blockIdx.y << 6;
    int bn  = blockIdx.x << 6;

    int aRow = tid >> 2;            // 0..63
    int aCol = (tid & 3) << 2;      // 0,4,8,12
    int bRow = tid >> 4;            // 0..15
    int bCol = (tid & 15) << 2;     // 0..60

    const float* Aptr = A + (size_t)(bm + aRow) * K + aCol;
    const float* Bptr = B + (size_t)bRow * N + bn + bCol;

    float acc[4][4] = {};

    for (int k0 = 0; k0 < K; k0 += 16) {
        float4 a4 = *(const float4*)(Aptr + k0);
        float4 b4 = *(const float4*)(Bptr + (size_t)k0 * N);
        As[aCol + 0][aRow] = a4.x;
        As[aCol + 1][aRow] = a4.y;
        As[aCol + 2][aRow] = a4.z;
        As[aCol + 3][aRow] = a4.w;
        *(float4*)&Bs[bRow][bCol] = b4;
        __syncthreads();
#pragma unroll
        for (int kk = 0; kk < 16; kk++) {
            float4 av = *(const float4*)&As[kk][ty << 2];
            float4 bv = *(const float4*)&Bs[kk][tx << 2];
            acc[0][0] += av.x*bv.x; acc[0][1] += av.x*bv.y; acc[0][2] += av.x*bv.z; acc[0][3] += av.x*bv.w;
            acc[1][0] += av.y*bv.x; acc[1][1] += av.y*bv.y; acc[1][2] += av.y*bv.z; acc[1][3] += av.y*bv.w;
            acc[2][0] += av.z*bv.x; acc[2][1] += av.z*bv.y; acc[2][2] += av.z*bv.z; acc[2][3] += av.z*bv.w;
            acc[3][0] += av.w*bv.x; acc[3][1] += av.w*bv.y; acc[3][2] += av.w*bv.z; acc[3][3] += av.w*bv.w;
        }
        __syncthreads();
    }

    float4 bi = *(const float4*)(bias + bn + (tx << 2));
#pragma unroll
    for (int i = 0; i < 4; i++) {
        int r = bm + (ty << 2) + i;
        float4 o;
        o.x = acc[i][0] + bi.x;
        o.y = acc[i][1] + bi.y;
        o.z = acc[i][2] + bi.z;
        o.w = acc[i][3] + bi.w;
        if (EPI == 0) {
            *(float4*)(Cd + (size_t)r * N + bn + (tx << 2)) = o;
        } else if (EPI == 1) {
            o.x = 0.5f * o.x * (1.0f + erff(o.x * 0.70710678118654752f));
            o.y = 0.5f * o.y * (1.0f + erff(o.y * 0.70710678118654752f));
            o.z = 0.5f * o.z * (1.0f + erff(o.z * 0.70710678118654752f));
            o.w = 0.5f * o.w * (1.0f + erff(o.w * 0.70710678118654752f));
            *(float4*)(Cd + (size_t)r * N + bn + (tx << 2)) = o;
        } else if (EPI == 2) {
            int dst = rowmap(r);
            size_t off = (size_t)dst * N + bn + (tx << 2);
            float4 rr = *(const float4*)(res + off);
            o.x += rr.x; o.y += rr.y; o.z += rr.z; o.w += rr.w;
            *(float4*)(Cd + off) = o;
        } else {  // EPI == 3
            size_t off = (size_t)r * N + bn + (tx << 2);
            float4 rr = *(const float4*)(res + off);
            o.x += rr.x; o.y += rr.y; o.z += rr.z; o.w += rr.w;
            *(float4*)(Cd + off) = o;
        }
    }
}

// ---------------- windowed attention: one block per (window, head) ----------------
__global__ void attn_kernel(const float* __restrict__ qkv,
                            const float* __restrict__ bias_table,  // [169, 8]
                            float* __restrict__ out)
{
    int h  = blockIdx.x & 7;
    int bw = blockIdx.x >> 3;          // 0..2047
    int widx = bw & 63;                // window index within image

    __shared__ float q[SDIM][DHEAD + 1];
    __shared__ float k[SDIM][DHEAD + 1];
    __shared__ float v[SDIM][DHEAD + 1];
    __shared__ float sc[SDIM][SDIM + 1];
    __shared__ float btab[169];
    __shared__ int   reg[SDIM];

    int tid = threadIdx.x;   // 128 threads

    for (int i = tid; i < 169; i += 128) btab[i] = bias_table[i * 8 + h];

    if (tid < SDIM) {
        int sy = tid / 7, sx = tid - sy * 7;
        int sh_h = ((widx >> 3) * 7) + sy;
        int sh_w = ((widx & 7) * 7) + sx;
        int fh = (sh_h < 49) ? 0 : ((sh_h < 53) ? 1 : 2);
        int fw = (sh_w < 49) ? 0 : ((sh_w < 53) ? 1 : 2);
        reg[tid] = (fw == 1) ? 0 : (fh * 3 + fw);
    }

    for (int i = tid; i < SDIM * DHEAD; i += 128) {
        int s = i >> 5, d = i & 31;
        size_t base = (size_t)(bw * 49 + s) * 768 + h * 32 + d;
        q[s][d] = qkv[base] * SCALE;
        k[s][d] = qkv[base + 256];
        v[s][d] = qkv[base + 512];
    }
    __syncthreads();

    for (int idx = tid; idx < SDIM * SDIM; idx += 128) {
        int s = idx / 49, t = idx - s * 49;
        float a = 0.0f;
#pragma unroll
        for (int d = 0; d < 32; d++) a += q[s][d] * k[t][d];
        int sy = s / 7, sx = s - sy * 7;
        int ty = t / 7, tx = t - ty * 7;
        a += btab[(sy - ty + 6) * 13 + (sx - tx + 6)];
        if (reg[s] != reg[t]) a -= 100.0f;
        sc[s][t] = a;
    }
    __syncthreads();

    if (tid < SDIM) {
        float mx = -1e30f;
        for (int t = 0; t < 49; t++) mx = fmaxf(mx, sc[tid][t]);
        float sum = 0.0f;
        for (int t = 0; t < 49; t++) {
            float e = expf(sc[tid][t] - mx);
            sc[tid][t] = e;
            sum += e;
        }
        float inv = 1.0f / sum;
        for (int t = 0; t < 49; t++) sc[tid][t] *= inv;
    }
    __syncthreads();

    for (int i = tid; i < SDIM * DHEAD; i += 128) {
        int s = i >> 5, d = i & 31;
        float a = 0.0f;
#pragma unroll 7
        for (int t = 0; t < 49; t++) a += sc[s][t] * v[t][d];
        out[(size_t)(bw * 49 + s) * 256 + h * 32 + d] = a;
    }
}

// ---------------- launch ----------------
extern "C" void kernel_launch(void* const* d_in, const int* in_sizes, int n_in,
                              void* d_out, int out_size)
{
    const float* x       = (const float*)d_in[0];
    const float* gamma   = (const float*)d_in[1];
    const float* beta    = (const float*)d_in[2];
    const float* qkv_w   = (const float*)d_in[3];
    const float* qkv_b   = (const float*)d_in[4];
    const float* proj_w  = (const float*)d_in[5];
    const float* proj_b  = (const float*)d_in[6];
    const float* relbias = (const float*)d_in[7];
    const float* mlp_w1  = (const float*)d_in[8];
    const float* mlp_b1  = (const float*)d_in[9];
    const float* mlp_w2  = (const float*)d_in[10];
    const float* mlp_b2  = (const float*)d_in[11];
    float* outp = (float*)d_out;

    float *xw, *qkvb, *attnb, *x1, *xn2, *hb;
    cudaGetSymbolAddress((void**)&xw,    g_xw);
    cudaGetSymbolAddress((void**)&qkvb,  g_qkv);
    cudaGetSymbolAddress((void**)&attnb, g_attn);
    cudaGetSymbolAddress((void**)&x1,    g_x1);
    cudaGetSymbolAddress((void**)&xn2,   g_xn2);
    cudaGetSymbolAddress((void**)&hb,    g_h);

    const int MROWS = TOKENS / 64;   // 1568

    // 1. LN + shift + window partition (gather)
    ln_kernel<true><<<TOKENS / 8, 256>>>(x, gamma, beta, xw);
    // 2. QKV projection
    gemm64<0><<<dim3(768 / 64, MROWS), 256>>>(xw, qkv_w, qkv_b, qkvb, nullptr, 768, 256);
    // 3. windowed attention
    attn_kernel<<<NWINTOT, 128>>>(qkvb, relbias, attnb);
    // 4. output projection + window reverse + unshift + residual
    gemm64<2><<<dim3(256 / 64, MROWS), 256>>>(attnb, proj_w, proj_b, x1, x, 256, 256);
    // 5. LN2
    ln_kernel<false><<<TOKENS / 8, 256>>>(x1, gamma, beta, xn2);
    // 6. MLP up + exact GELU
    gemm64<1><<<dim3(1024 / 64, MROWS), 256>>>(xn2, mlp_w1, mlp_b1, hb, nullptr, 1024, 256);
    // 7. MLP down + residual -> output
    gemm64<3><<<dim3(256 / 64, MROWS), 256>>>(hb, mlp_w2, mlp_b2, outp, x1, 256, 1024);
}

// round 3
// speedup vs baseline: 2.1860x; 2.1860x over previous
#include <cuda_runtime.h>
#include <math.h>
#include <stdint.h>

// ---------------- static problem config ----------------
#define TOKENS   100352      // 32 * 56 * 56  == 2048 windows * 49
#define CDIM     256
#define SDIM     49
#define IMG      56
#define WIN      7
#define SHIFT    3
#define NMLP     1024
#define NWINTOT  16384       // 2048 windows * 8 heads
#define SCALE    0.17677669529663687f

// ---------------- device scratch ----------------
__device__ float g_xw  [TOKENS * CDIM];
__device__ float g_qkv [TOKENS * 3 * CDIM];
__device__ float g_attn[TOKENS * CDIM];
__device__ float g_x1  [TOKENS * CDIM];
__device__ float g_xn2 [TOKENS * CDIM];
__device__ float g_h   [TOKENS * NMLP];
__device__ float g_wT  [768*256 + 256*256 + 1024*256 + 256*1024];

#define WT_QKV  0
#define WT_PROJ (768*256)
#define WT_W1   (768*256 + 256*256)
#define WT_W2   (768*256 + 256*256 + 1024*256)

// ---------------- helpers ----------------
__device__ __forceinline__ uint32_t smem_u32(const void* p) {
    uint32_t a;
    asm("{ .reg .u64 t; cvta.to.shared.u64 t, %1; cvt.u32.u64 %0, t; }" : "=r"(a) : "l"(p));
    return a;
}
__device__ __forceinline__ float tf32r(float x) {
    uint32_t u; asm("cvt.rna.tf32.f32 %0, %1;" : "=r"(u) : "f"(x));
    return __uint_as_float(u);
}
__device__ __forceinline__ void cp_async16(uint32_t dst, const void* src) {
    asm volatile("cp.async.cg.shared.global [%0], [%1], 16;" :: "r"(dst), "l"(src));
}
__device__ __forceinline__ void mma_tf32(float* c, const uint32_t* a, const uint32_t* b) {
    asm volatile(
        "mma.sync.aligned.m16n8k8.row.col.f32.tf32.tf32.f32 "
        "{%0,%1,%2,%3}, {%4,%5,%6,%7}, {%8,%9}, {%0,%1,%2,%3};"
        : "+f"(c[0]), "+f"(c[1]), "+f"(c[2]), "+f"(c[3])
        : "r"(a[0]), "r"(a[1]), "r"(a[2]), "r"(a[3]), "r"(b[0]), "r"(b[1]));
}

// window-order row -> token-order row (roll+partition == reverse+unroll mapping)
__device__ __forceinline__ int rowmap(int r) {
    int bw = r / 49;
    int s  = r - bw * 49;
    int b    = bw >> 6;
    int widx = bw & 63;
    int sy = s / 7, sx = s - sy * 7;
    int sh_h = ((widx >> 3) * 7) + sy;
    int sh_w = ((widx & 7) * 7) + sx;
    int oh = sh_h + SHIFT; if (oh >= IMG) oh -= IMG;
    int ow = sh_w + SHIFT; if (ow >= IMG) ow -= IMG;
    return b * (IMG * IMG) + oh * IMG + ow;
}

// ---------------- weight transpose (tf32-rounded): in[K][N] -> out[N][K] ----------------
__global__ void transpose_k(const float* __restrict__ in, float* __restrict__ out,
                            int K, int N)
{
    __shared__ float t[32][33];
    int n0 = blockIdx.x << 5, k0 = blockIdx.y << 5;
    int x = threadIdx.x, y = threadIdx.y;          // 32 x 8
#pragma unroll
    for (int dy = 0; dy < 32; dy += 8)
        t[y + dy][x] = in[(size_t)(k0 + y + dy) * N + n0 + x];
    __syncthreads();
#pragma unroll
    for (int dy = 0; dy < 32; dy += 8)
        out[(size_t)(n0 + y + dy) * K + k0 + x] = tf32r(t[x][y + dy]);
}

// ---------------- LayerNorm (warp per token), tf32-rounded output ----------------
template<bool GATHER>
__global__ void ln_kernel(const float* __restrict__ x,
                          const float* __restrict__ gamma,
                          const float* __restrict__ beta,
                          float* __restrict__ out)
{
    int gw   = (blockIdx.x * blockDim.x + threadIdx.x) >> 5;
    int lane = threadIdx.x & 31;
    if (gw >= TOKENS) return;

    int src = GATHER ? rowmap(gw) : gw;
    const float4* xr = (const float4*)(x + (size_t)src * CDIM);
    float4 v0 = xr[lane];
    float4 v1 = xr[lane + 32];

    float sum = v0.x + v0.y + v0.z + v0.w + v1.x + v1.y + v1.z + v1.w;
    float sq  = v0.x*v0.x + v0.y*v0.y + v0.z*v0.z + v0.w*v0.w
              + v1.x*v1.x + v1.y*v1.y + v1.z*v1.z + v1.w*v1.w;
#pragma unroll
    for (int o = 16; o; o >>= 1) {
        sum += __shfl_xor_sync(0xffffffffu, sum, o);
        sq  += __shfl_xor_sync(0xffffffffu, sq,  o);
    }
    float mu   = sum * (1.0f / 256.0f);
    float var  = sq * (1.0f / 256.0f) - mu * mu;
    float rstd = rsqrtf(var + 1e-5f);

    float4 g0 = ((const float4*)gamma)[lane];
    float4 g1 = ((const float4*)gamma)[lane + 32];
    float4 b0 = ((const float4*)beta )[lane];
    float4 b1 = ((const float4*)beta )[lane + 32];

    float4 o0, o1;
    o0.x = tf32r((v0.x - mu) * rstd * g0.x + b0.x);
    o0.y = tf32r((v0.y - mu) * rstd * g0.y + b0.y);
    o0.z = tf32r((v0.z - mu) * rstd * g0.z + b0.z);
    o0.w = tf32r((v0.w - mu) * rstd * g0.w + b0.w);
    o1.x = tf32r((v1.x - mu) * rstd * g1.x + b1.x);
    o1.y = tf32r((v1.y - mu) * rstd * g1.y + b1.y);
    o1.z = tf32r((v1.z - mu) * rstd * g1.z + b1.z);
    o1.w = tf32r((v1.w - mu) * rstd * g1.w + b1.w);

    float4* orow = (float4*)(out + (size_t)gw * CDIM);
    orow[lane]      = o0;
    orow[lane + 32] = o1;
}

// ---------------- tf32 mma.sync GEMM: C[M,N] = A[M,K] @ Bt[N,K]^T + bias ----------------
// Block 128x128, 8 warps (2m x 4n), warp tile 64x32, k-chunk 16, 2-stage cp.async.
// EPI 0: store   EPI 1: exact GELU + tf32 round   EPI 2: scatter+residual   EPI 3: residual
template<int EPI>
__global__ void __launch_bounds__(256)
tc_gemm(const float* __restrict__ A,
        const float* __restrict__ Bt,
        const float* __restrict__ bias,
        float* __restrict__ Cd,
        const float* __restrict__ res,
        int N, int K)
{
    __shared__ float As[2][128][20];
    __shared__ float Bs[2][128][20];

    int tid  = threadIdx.x;
    int lane = tid & 31;
    int wid  = tid >> 5;
    int wm   = wid >> 2;          // 0..1  (64 rows each)
    int wn   = wid & 3;           // 0..3  (32 cols each)
    int bm   = blockIdx.y << 7;
    int bn   = blockIdx.x << 7;

    int lrow = tid >> 2;          // 0..63
    int k4   = (tid & 3) << 2;    // 0,4,8,12

    const float* Ag = A  + (size_t)(bm + lrow) * K + k4;
    const float* Bg = Bt + (size_t)(bn + lrow) * K + k4;

    float acc[4][4][4];
#pragma unroll
    for (int mt = 0; mt < 4; mt++)
#pragma unroll
        for (int nt = 0; nt < 4; nt++)
#pragma unroll
            for (int i = 0; i < 4; i++) acc[mt][nt][i] = 0.0f;

    const int nch = K >> 4;

    // prefetch chunk 0
    {
        cp_async16(smem_u32(&As[0][lrow][k4]),      Ag);
        cp_async16(smem_u32(&As[0][lrow + 64][k4]), Ag + (size_t)64 * K);
        cp_async16(smem_u32(&Bs[0][lrow][k4]),      Bg);
        cp_async16(smem_u32(&Bs[0][lrow + 64][k4]), Bg + (size_t)64 * K);
        asm volatile("cp.async.commit_group;" ::: "memory");
    }

    for (int c = 0; c < nch; ++c) {
        if (c + 1 < nch) {
            int nb = (c + 1) & 1;
            int k0 = (c + 1) << 4;
            cp_async16(smem_u32(&As[nb][lrow][k4]),      Ag + k0);
            cp_async16(smem_u32(&As[nb][lrow + 64][k4]), Ag + (size_t)64 * K + k0);
            cp_async16(smem_u32(&Bs[nb][lrow][k4]),      Bg + k0);
            cp_async16(smem_u32(&Bs[nb][lrow + 64][k4]), Bg + (size_t)64 * K + k0);
            asm volatile("cp.async.commit_group;" ::: "memory");
            asm volatile("cp.async.wait_group 1;" ::: "memory");
        } else {
            asm volatile("cp.async.wait_group 0;" ::: "memory");
        }
        __syncthreads();

        int buf = c & 1;
#pragma unroll
        for (int kk = 0; kk < 16; kk += 8) {
            uint32_t afr[4][4], bfr[4][2];
            int q = lane >> 2, p = lane & 3;
#pragma unroll
            for (int mt = 0; mt < 4; mt++) {
                int r0 = wm * 64 + mt * 16 + q;
                afr[mt][0] = __float_as_uint(As[buf][r0    ][kk + p    ]);
                afr[mt][1] = __float_as_uint(As[buf][r0 + 8][kk + p    ]);
                afr[mt][2] = __float_as_uint(As[buf][r0    ][kk + p + 4]);
                afr[mt][3] = __float_as_uint(As[buf][r0 + 8][kk + p + 4]);
            }
#pragma unroll
            for (int nt = 0; nt < 4; nt++) {
                int n0 = wn * 32 + nt * 8 + q;
                bfr[nt][0] = __float_as_uint(Bs[buf][n0][kk + p    ]);
                bfr[nt][1] = __float_as_uint(Bs[buf][n0][kk + p + 4]);
            }
#pragma unroll
            for (int mt = 0; mt < 4; mt++)
#pragma unroll
                for (int nt = 0; nt < 4; nt++)
                    mma_tf32(acc[mt][nt], afr[mt], bfr[nt]);
        }
        __syncthreads();
    }

    // ---------------- epilogue ----------------
    int q = lane >> 2, p = lane & 3;
#pragma unroll
    for (int mt = 0; mt < 4; mt++) {
#pragma unroll
        for (int half = 0; half < 2; half++) {
            int r   = bm + wm * 64 + mt * 16 + q + half * 8;
            int dst = (EPI == 2) ? rowmap(r) : r;
            size_t rowbase = (size_t)dst * N;
#pragma unroll
            for (int nt = 0; nt < 4; nt++) {
                int col = bn + wn * 32 + nt * 8 + p * 2;
                float x0 = acc[mt][nt][half * 2 + 0];
                float x1 = acc[mt][nt][half * 2 + 1];
                float2 bi = *(const float2*)(bias + col);
                x0 += bi.x; x1 += bi.y;
                if (EPI == 1) {
                    x0 = tf32r(0.5f * x0 * (1.0f + erff(x0 * 0.70710678118654752f)));
                    x1 = tf32r(0.5f * x1 * (1.0f + erff(x1 * 0.70710678118654752f)));
                } else if (EPI >= 2) {
                    float2 rr = *(const float2*)(res + rowbase + col);
                    x0 += rr.x; x1 += rr.y;
                }
                float2 o; o.x = x0; o.y = x1;
                *(float2*)(Cd + rowbase + col) = o;
            }
        }
    }
}

// ---------------- windowed attention (tf32-rounded output) ----------------
__global__ void attn_kernel(const float* __restrict__ qkv,
                            const float* __restrict__ bias_table,
                            float* __restrict__ out)
{
    int h  = blockIdx.x & 7;
    int bw = blockIdx.x >> 3;
    int widx = bw & 63;

    __shared__ float q[SDIM][33];
    __shared__ float k[SDIM][33];
    __shared__ float v[SDIM][33];
    __shared__ float sc[SDIM][SDIM + 1];
    __shared__ float btab[169];
    __shared__ int   reg[SDIM];

    int tid = threadIdx.x;

    for (int i = tid; i < 169; i += 128) btab[i] = bias_table[i * 8 + h];

    if (tid < SDIM) {
        int sy = tid / 7, sx = tid - sy * 7;
        int sh_h = ((widx >> 3) * 7) + sy;
        int sh_w = ((widx & 7) * 7) + sx;
        int fh = (sh_h < 49) ? 0 : ((sh_h < 53) ? 1 : 2);
        int fw = (sh_w < 49) ? 0 : ((sh_w < 53) ? 1 : 2);
        reg[tid] = (fw == 1) ? 0 : (fh * 3 + fw);
    }

    for (int i = tid; i < SDIM * 32; i += 128) {
        int s = i >> 5, d = i & 31;
        size_t base = (size_t)(bw * 49 + s) * 768 + h * 32 + d;
        q[s][d] = qkv[base] * SCALE;
        k[s][d] = qkv[base + 256];
        v[s][d] = qkv[base + 512];
    }
    __syncthreads();

    for (int idx = tid; idx < SDIM * SDIM; idx += 128) {
        int s = idx / 49, t = idx - s * 49;
        float a = 0.0f;
#pragma unroll
        for (int d = 0; d < 32; d++) a += q[s][d] * k[t][d];
        int sy = s / 7, sx = s - sy * 7;
        int ty = t / 7, tx = t - ty * 7;
        a += btab[(sy - ty + 6) * 13 + (sx - tx + 6)];
        if (reg[s] != reg[t]) a -= 100.0f;
        sc[s][t] = a;
    }
    __syncthreads();

    if (tid < SDIM) {
        float mx = -1e30f;
        for (int t = 0; t < 49; t++) mx = fmaxf(mx, sc[tid][t]);
        float sum = 0.0f;
        for (int t = 0; t < 49; t++) {
            float e = expf(sc[tid][t] - mx);
            sc[tid][t] = e;
            sum += e;
        }
        float inv = 1.0f / sum;
        for (int t = 0; t < 49; t++) sc[tid][t] *= inv;
    }
    __syncthreads();

    for (int i = tid; i < SDIM * 32; i += 128) {
        int s = i >> 5, d = i & 31;
        float a = 0.0f;
#pragma unroll 7
        for (int t = 0; t < 49; t++) a += sc[s][t] * v[t][d];
        out[(size_t)(bw * 49 + s) * 256 + h * 32 + d] = tf32r(a);
    }
}

// ---------------- launch ----------------
extern "C" void kernel_launch(void* const* d_in, const int* in_sizes, int n_in,
                              void* d_out, int out_size)
{
    const float* x       = (const float*)d_in[0];
    const float* gamma   = (const float*)d_in[1];
    const float* beta    = (const float*)d_in[2];
    const float* qkv_w   = (const float*)d_in[3];
    const float* qkv_b   = (const float*)d_in[4];
    const float* proj_w  = (const float*)d_in[5];
    const float* proj_b  = (const float*)d_in[6];
    const float* relbias = (const float*)d_in[7];
    const float* mlp_w1  = (const float*)d_in[8];
    const float* mlp_b1  = (const float*)d_in[9];
    const float* mlp_w2  = (const float*)d_in[10];
    const float* mlp_b2  = (const float*)d_in[11];
    float* outp = (float*)d_out;

    float *xw, *qkvb, *attnb, *x1, *xn2, *hb, *wT;
    cudaGetSymbolAddress((void**)&xw,    g_xw);
    cudaGetSymbolAddress((void**)&qkvb,  g_qkv);
    cudaGetSymbolAddress((void**)&attnb, g_attn);
    cudaGetSymbolAddress((void**)&x1,    g_x1);
    cudaGetSymbolAddress((void**)&xn2,   g_xn2);
    cudaGetSymbolAddress((void**)&hb,    g_h);
    cudaGetSymbolAddress((void**)&wT,    g_wT);

    const int MT = TOKENS / 128;   // 784

    // weight transposes (tf32-rounded, [N,K] K-major layout)
    transpose_k<<<dim3(768/32, 256/32),  dim3(32,8)>>>(qkv_w,  wT + WT_QKV,  256, 768);
    transpose_k<<<dim3(256/32, 256/32),  dim3(32,8)>>>(proj_w, wT + WT_PROJ, 256, 256);
    transpose_k<<<dim3(1024/32, 256/32), dim3(32,8)>>>(mlp_w1, wT + WT_W1,   256, 1024);
    transpose_k<<<dim3(256/32, 1024/32), dim3(32,8)>>>(mlp_w2, wT + WT_W2,   1024, 256);

    // 1. LN + shift + window partition (gather)
    ln_kernel<true><<<TOKENS / 8, 256>>>(x, gamma, beta, xw);
    // 2. QKV projection (tf32 tensor cores)
    tc_gemm<0><<<dim3(6, MT), 256>>>(xw, wT + WT_QKV, qkv_b, qkvb, nullptr, 768, 256);
    // 3. windowed attention
    attn_kernel<<<NWINTOT, 128>>>(qkvb, relbias, attnb);
    // 4. output projection + window reverse + unshift + residual
    tc_gemm<2><<<dim3(2, MT), 256>>>(attnb, wT + WT_PROJ, proj_b, x1, x, 256, 256);
    // 5. LN2
    ln_kernel<false><<<TOKENS / 8, 256>>>(x1, gamma, beta, xn2);
    // 6. MLP up + exact GELU
    tc_gemm<1><<<dim3(8, MT), 256>>>(xn2, wT + WT_W1, mlp_b1, hb, nullptr, 1024, 256);
    // 7. MLP down + residual -> output
    tc_gemm<3><<<dim3(2, MT), 256>>>(hb, wT + WT_W2, mlp_b2, outp, x1, 256, 1024);
}